// round 10
// baseline (speedup 1.0000x reference)
#include <cuda_runtime.h>
#include <math.h>

// Problem dims (fixed by the reference)
#define NB 8192   // batch
#define NE 256    // embedding
#define NH 4096   // hidden
#define BN_EPS 1e-5f

// ---------------------------------------------------------------------------
// Scratch (device globals: allocation-free)
// ---------------------------------------------------------------------------
__device__ float g_H[2][NB * NH];          // 256 MB: pre-BN hidden for each view
__device__ float g_Q[2][NB * NE];          // 16 MB: predictor outputs q1, q2
__device__ float g_psum[2][32][NH];        // per-rowblock partial column sums
__device__ float g_psumsq[2][32][NH];
__device__ float g_scale[2][NH];           // fused BN scale  = rstd*gamma
__device__ float g_shift[2][NH];           // fused BN shift  = beta - mu*scale
__device__ float g_inorm[4][NB];           // inverse row norms: p1,p2,q1,q2
__device__ float g_Mp[2][8][NE * NE];      // split-K partials of M
__device__ float g_M[2][NE * NE];          // M = v2^T v1 / lamda_inv  (256x256)
__device__ float g_M2[2][NE * NE];         // M @ M
__device__ float g_tp[2][32][4];           // partial traces t1..t4 per block

// ---------------------------------------------------------------------------
// GEMM1: H[v] = z_v @ W1     (8192x256) @ (256x4096)
// 128x128 tile, BK=8, 256 threads, 8x8 per thread
// ---------------------------------------------------------------------------
__global__ __launch_bounds__(256, 2) void k_gemm1(const float* __restrict__ z1,
                                                  const float* __restrict__ z2,
                                                  const float* __restrict__ W1)
{
    const int v = blockIdx.z;
    const float* __restrict__ A = v ? z2 : z1;   // [NB, NE]
    float* __restrict__ C = g_H[v];              // [NB, NH]

    __shared__ float As[8][128];
    __shared__ float Bs[8][128];

    const int tid = threadIdx.x;
    const int tx = tid & 15;
    const int ty = tid >> 4;
    const int m0 = blockIdx.y * 128;
    const int n0 = blockIdx.x * 128;

    const int ar = tid >> 1;          // 0..127 row within A tile
    const int ak = (tid & 1) * 4;     // 0 or 4 k-offset
    const int br = tid >> 5;          // 0..7 k-row within B tile
    const int bn = (tid & 31) * 4;    // col within B tile

    float acc[8][8];
#pragma unroll
    for (int i = 0; i < 8; i++)
#pragma unroll
        for (int j = 0; j < 8; j++) acc[i][j] = 0.f;

    const float* Aptr = A + (m0 + ar) * NE + ak;
    const float* Bptr = W1 + br * NH + n0 + bn;

    for (int k0 = 0; k0 < NE; k0 += 8) {
        float4 a4 = *(const float4*)(Aptr + k0);
        float4 b4 = *(const float4*)(Bptr + (size_t)k0 * NH);
        __syncthreads();
        As[ak + 0][ar] = a4.x;
        As[ak + 1][ar] = a4.y;
        As[ak + 2][ar] = a4.z;
        As[ak + 3][ar] = a4.w;
        *(float4*)&Bs[br][bn] = b4;
        __syncthreads();
#pragma unroll
        for (int k = 0; k < 8; k++) {
            float a[8], b[8];
            *(float4*)(a)     = *(const float4*)&As[k][ty * 8];
            *(float4*)(a + 4) = *(const float4*)&As[k][ty * 8 + 4];
            *(float4*)(b)     = *(const float4*)&Bs[k][tx * 8];
            *(float4*)(b + 4) = *(const float4*)&Bs[k][tx * 8 + 4];
#pragma unroll
            for (int i = 0; i < 8; i++)
#pragma unroll
                for (int j = 0; j < 8; j++)
                    acc[i][j] = fmaf(a[i], b[j], acc[i][j]);
        }
    }

#pragma unroll
    for (int i = 0; i < 8; i++) {
        float* crow = C + (size_t)(m0 + ty * 8 + i) * NH + n0 + tx * 8;
        *(float4*)crow = make_float4(acc[i][0], acc[i][1], acc[i][2], acc[i][3]);
        *((float4*)crow + 1) = make_float4(acc[i][4], acc[i][5], acc[i][6], acc[i][7]);
    }
}

// ---------------------------------------------------------------------------
// BN statistics: partial column sums over 256-row blocks (deterministic)
// grid (NH/256, 32, 2)
// ---------------------------------------------------------------------------
__global__ __launch_bounds__(256) void k_bnstats()
{
    const int v = blockIdx.z;
    const int col = blockIdx.x * 256 + threadIdx.x;
    const int r0 = blockIdx.y * 256;
    const float* A = g_H[v] + (size_t)r0 * NH + col;
    float s = 0.f, s2 = 0.f;
#pragma unroll 4
    for (int r = 0; r < 256; r++) {
        float x = A[(size_t)r * NH];
        s += x;
        s2 = fmaf(x, x, s2);
    }
    g_psum[v][blockIdx.y][col] = s;
    g_psumsq[v][blockIdx.y][col] = s2;
}

// Finalize BN: scale/shift per (view, hidden unit). grid 32 x 256 threads.
__global__ void k_bnfin(const float* __restrict__ gamma,
                        const float* __restrict__ beta)
{
    int i = blockIdx.x * 256 + threadIdx.x;  // 0 .. 2*NH-1
    int v = i >> 12;
    int h = i & (NH - 1);
    float s = 0.f, s2 = 0.f;
#pragma unroll
    for (int b = 0; b < 32; b++) {
        s += g_psum[v][b][h];
        s2 += g_psumsq[v][b][h];
    }
    float mu = s * (1.f / NB);
    float var = s2 * (1.f / NB) - mu * mu;
    float scl = rsqrtf(var + BN_EPS) * gamma[h];
    g_scale[v][h] = scl;
    g_shift[v][h] = fmaf(-mu, scl, beta[h]);
}

// ---------------------------------------------------------------------------
// GEMM2: Q[v] = relu(bn(H[v])) @ W2 + b2   (8192x4096)@(4096x256)
// BN+ReLU fused into A-tile load. grid (2, 64, 2)
// ---------------------------------------------------------------------------
__global__ __launch_bounds__(256, 2) void k_gemm2(const float* __restrict__ W2,
                                                  const float* __restrict__ b2)
{
    const int v = blockIdx.z;
    const float* __restrict__ A = g_H[v];
    const float* __restrict__ sc = g_scale[v];
    const float* __restrict__ sh = g_shift[v];
    float* __restrict__ C = g_Q[v];

    __shared__ float As[8][128];
    __shared__ float Bs[8][128];

    const int tid = threadIdx.x;
    const int tx = tid & 15;
    const int ty = tid >> 4;
    const int m0 = blockIdx.y * 128;
    const int n0 = blockIdx.x * 128;

    const int ar = tid >> 1;
    const int ak = (tid & 1) * 4;
    const int br = tid >> 5;
    const int bn = (tid & 31) * 4;

    float acc[8][8];
#pragma unroll
    for (int i = 0; i < 8; i++)
#pragma unroll
        for (int j = 0; j < 8; j++) acc[i][j] = 0.f;

    const float* Aptr = A + (size_t)(m0 + ar) * NH + ak;
    const float* Bptr = W2 + br * NE + n0 + bn;

    for (int k0 = 0; k0 < NH; k0 += 8) {
        float4 h4 = *(const float4*)(Aptr + k0);
        float4 s4 = *(const float4*)(sc + k0 + ak);
        float4 t4 = *(const float4*)(sh + k0 + ak);
        float4 b4 = *(const float4*)(Bptr + (size_t)k0 * NE);
        float4 a4;
        a4.x = fmaxf(fmaf(h4.x, s4.x, t4.x), 0.f);
        a4.y = fmaxf(fmaf(h4.y, s4.y, t4.y), 0.f);
        a4.z = fmaxf(fmaf(h4.z, s4.z, t4.z), 0.f);
        a4.w = fmaxf(fmaf(h4.w, s4.w, t4.w), 0.f);
        __syncthreads();
        As[ak + 0][ar] = a4.x;
        As[ak + 1][ar] = a4.y;
        As[ak + 2][ar] = a4.z;
        As[ak + 3][ar] = a4.w;
        *(float4*)&Bs[br][bn] = b4;
        __syncthreads();
#pragma unroll
        for (int k = 0; k < 8; k++) {
            float a[8], b[8];
            *(float4*)(a)     = *(const float4*)&As[k][ty * 8];
            *(float4*)(a + 4) = *(const float4*)&As[k][ty * 8 + 4];
            *(float4*)(b)     = *(const float4*)&Bs[k][tx * 8];
            *(float4*)(b + 4) = *(const float4*)&Bs[k][tx * 8 + 4];
#pragma unroll
            for (int i = 0; i < 8; i++)
#pragma unroll
                for (int j = 0; j < 8; j++)
                    acc[i][j] = fmaf(a[i], b[j], acc[i][j]);
        }
    }

    float bias[8];
    *(float4*)(bias)     = *(const float4*)(b2 + n0 + tx * 8);
    *(float4*)(bias + 4) = *(const float4*)(b2 + n0 + tx * 8 + 4);

#pragma unroll
    for (int i = 0; i < 8; i++) {
        float* crow = C + (size_t)(m0 + ty * 8 + i) * NE + n0 + tx * 8;
        *(float4*)crow = make_float4(acc[i][0] + bias[0], acc[i][1] + bias[1],
                                     acc[i][2] + bias[2], acc[i][3] + bias[3]);
        *((float4*)crow + 1) = make_float4(acc[i][4] + bias[4], acc[i][5] + bias[5],
                                           acc[i][6] + bias[6], acc[i][7] + bias[7]);
    }
}

// ---------------------------------------------------------------------------
// Row inverse L2 norms for p1, p2, q1, q2.  One warp per row.
// grid (NB/8, 4), 256 threads
// ---------------------------------------------------------------------------
__global__ __launch_bounds__(256) void k_norms(const float* __restrict__ p1,
                                               const float* __restrict__ p2)
{
    int mat = blockIdx.y;
    const float* X = (mat == 0) ? p1 : (mat == 1) ? p2 : g_Q[mat - 2];
    int row = blockIdx.x * 8 + (threadIdx.x >> 5);
    int lane = threadIdx.x & 31;
    const float* xr = X + (size_t)row * NE;
    float s = 0.f;
#pragma unroll
    for (int j = 0; j < NE; j += 32) {
        float x = xr[j + lane];
        s = fmaf(x, x, s);
    }
#pragma unroll
    for (int o = 16; o; o >>= 1) s += __shfl_xor_sync(0xffffffffu, s, o);
    if (lane == 0) g_inorm[mat][row] = 1.f / fmaxf(sqrtf(s), 1e-12f);
}

// ---------------------------------------------------------------------------
// M partials: for mec m, M[i][j] = sum_b v2n[b][i] * v1n[b][j]
// mec 0: v1 = p1n, v2 = q2n ; mec 1: v1 = p2n, v2 = q1n
// 64x64 tile, BK=16, split-K by 8. grid (4, 4, 16)
// ---------------------------------------------------------------------------
__global__ __launch_bounds__(256) void k_gemmM(const float* __restrict__ p1,
                                               const float* __restrict__ p2)
{
    const int z = blockIdx.z;
    const int m = z >> 3;
    const int ks = z & 7;
    const float* A  = m ? g_Q[0] : g_Q[1];      // v2 source (i index)
    const float* ia = m ? g_inorm[2] : g_inorm[3];
    const float* Bm = m ? p2 : p1;              // v1 source (j index)
    const float* ib = m ? g_inorm[1] : g_inorm[0];

    __shared__ float As[16][64];
    __shared__ float Bs[16][64];

    const int tid = threadIdx.x;
    const int tx = tid & 15;
    const int ty = tid >> 4;
    const int i0 = blockIdx.y * 64;
    const int j0 = blockIdx.x * 64;
    const int lk = tid >> 4;          // 0..15  (k row of tile)
    const int lc = (tid & 15) * 4;    // col within tile

    float acc[4][4] = {};

    const int kend = ks * 1024 + 1024;
    for (int kb = ks * 1024; kb < kend; kb += 16) {
        int b = kb + lk;
        float na = ia[b], nb = ib[b];
        float4 av = *(const float4*)(A + (size_t)b * NE + i0 + lc);
        float4 bv = *(const float4*)(Bm + (size_t)b * NE + j0 + lc);
        __syncthreads();
        *(float4*)&As[lk][lc] = make_float4(av.x * na, av.y * na, av.z * na, av.w * na);
        *(float4*)&Bs[lk][lc] = make_float4(bv.x * nb, bv.y * nb, bv.z * nb, bv.w * nb);
        __syncthreads();
#pragma unroll
        for (int k = 0; k < 16; k++) {
            float a[4], bb[4];
            *(float4*)a  = *(const float4*)&As[k][ty * 4];
            *(float4*)bb = *(const float4*)&Bs[k][tx * 4];
#pragma unroll
            for (int ii = 0; ii < 4; ii++)
#pragma unroll
                for (int jj = 0; jj < 4; jj++)
                    acc[ii][jj] = fmaf(a[ii], bb[jj], acc[ii][jj]);
        }
    }

    float* O = g_Mp[m][ks];
#pragma unroll
    for (int ii = 0; ii < 4; ii++)
#pragma unroll
        for (int jj = 0; jj < 4; jj++)
            O[(i0 + ty * 4 + ii) * NE + j0 + tx * 4 + jj] = acc[ii][jj];
}

// Reduce split-K partials and apply 1/lamda_inv. grid (256, 2)
__global__ void k_Mred(const float* __restrict__ plam)
{
    int m = blockIdx.y;
    int i = blockIdx.x * 256 + threadIdx.x;   // 0..65535
    float inv = 1.f / *plam;
    float s = 0.f;
#pragma unroll
    for (int ks = 0; ks < 8; ks++) s += g_Mp[m][ks][i];
    g_M[m][i] = s * inv;
}

// ---------------------------------------------------------------------------
// M2 = M @ M   (256x256x256). grid (4, 4, 2), 64x64 tiles, BK=16
// ---------------------------------------------------------------------------
__global__ __launch_bounds__(256) void k_M2()
{
    const int m = blockIdx.z;
    const float* M = g_M[m];
    float* O = g_M2[m];

    __shared__ float As[16][64];
    __shared__ float Bs[16][64];

    const int tid = threadIdx.x;
    const int tx = tid & 15;
    const int ty = tid >> 4;
    const int i0 = blockIdx.y * 64;
    const int j0 = blockIdx.x * 64;
    const int ai = tid >> 2;           // 0..63  row of A tile
    const int ak = (tid & 3) * 4;      // k offset (0..12)
    const int bk = tid >> 4;           // 0..15
    const int bj = (tid & 15) * 4;

    float acc[4][4] = {};

    for (int kb = 0; kb < NE; kb += 16) {
        float4 av = *(const float4*)(M + (i0 + ai) * NE + kb + ak);
        float4 bv = *(const float4*)(M + (kb + bk) * NE + j0 + bj);
        __syncthreads();
        As[ak + 0][ai] = av.x;
        As[ak + 1][ai] = av.y;
        As[ak + 2][ai] = av.z;
        As[ak + 3][ai] = av.w;
        *(float4*)&Bs[bk][bj] = bv;
        __syncthreads();
#pragma unroll
        for (int k = 0; k < 16; k++) {
            float a[4], bb[4];
            *(float4*)a  = *(const float4*)&As[k][ty * 4];
            *(float4*)bb = *(const float4*)&Bs[k][tx * 4];
#pragma unroll
            for (int ii = 0; ii < 4; ii++)
#pragma unroll
                for (int jj = 0; jj < 4; jj++)
                    acc[ii][jj] = fmaf(a[ii], bb[jj], acc[ii][jj]);
        }
    }

#pragma unroll
    for (int ii = 0; ii < 4; ii++)
#pragma unroll
        for (int jj = 0; jj < 4; jj++)
            O[(i0 + ty * 4 + ii) * NE + j0 + tx * 4 + jj] = acc[ii][jj];
}

// ---------------------------------------------------------------------------
// Traces: t1=tr(M), t2=tr(M^2), t3=tr(M^3)=<M2, M^T>, t4=tr(M^4)=<M2, M2^T>
// grid (32, 2), each block handles 2048 elements, writes partials
// ---------------------------------------------------------------------------
__global__ __launch_bounds__(256) void k_traces()
{
    const int m = blockIdx.y;
    const float* M = g_M[m];
    const float* M2 = g_M2[m];
    const int tid = threadIdx.x;
    const int idx0 = blockIdx.x * 2048;

    float t1 = 0.f, t2 = 0.f, t3 = 0.f, t4 = 0.f;
    for (int idx = idx0 + tid; idx < idx0 + 2048; idx += 256) {
        int i = idx >> 8;
        int j = idx & 255;
        float mij = M[idx];
        float mji = M[j * NE + i];
        float m2ij = M2[idx];
        float m2ji = M2[j * NE + i];
        if (i == j) t1 += mij;
        t2 = fmaf(mij, mji, t2);
        t3 = fmaf(m2ij, mji, t3);
        t4 = fmaf(m2ij, m2ji, t4);
    }

    __shared__ float red[4][256];
    red[0][tid] = t1; red[1][tid] = t2; red[2][tid] = t3; red[3][tid] = t4;
    __syncthreads();
    for (int s = 128; s > 0; s >>= 1) {
        if (tid < s) {
            red[0][tid] += red[0][tid + s];
            red[1][tid] += red[1][tid + s];
            red[2][tid] += red[2][tid + s];
            red[3][tid] += red[3][tid + s];
        }
        __syncthreads();
    }
    if (tid < 4) g_tp[m][blockIdx.x][tid] = red[tid][0];
}

// Final scalar: sum partials, Taylor combine, scale. 1 thread.
__global__ void k_final(const float* __restrict__ plam, float* __restrict__ out)
{
    float t[2][4];
    for (int m = 0; m < 2; m++)
        for (int c = 0; c < 4; c++) {
            float s = 0.f;
            for (int b = 0; b < 32; b++) s += g_tp[m][b][c];
            t[m][c] = s;
        }
    // sum_k sign_k * tr(c^k)/k with sign: k=1:+, 2:-, 3:+, 4:-
    float s0 = t[0][0] - 0.5f * t[0][1] + (1.f / 3.f) * t[0][2] - 0.25f * t[0][3];
    float s1 = t[1][0] - 0.5f * t[1][1] + (1.f / 3.f) * t[1][2] - 0.25f * t[1][3];
    float loss = (s0 + s1) * 0.5f / (float)NB;
    out[0] = -loss * (*plam);
}

// ---------------------------------------------------------------------------
// Launch
// ---------------------------------------------------------------------------
extern "C" void kernel_launch(void* const* d_in, const int* in_sizes, int n_in,
                              void* d_out, int out_size)
{
    const float* z1    = (const float*)d_in[0];
    const float* z2    = (const float*)d_in[1];
    const float* p1    = (const float*)d_in[2];
    const float* p2    = (const float*)d_in[3];
    const float* W1    = (const float*)d_in[4];
    const float* gamma = (const float*)d_in[5];
    const float* beta  = (const float*)d_in[6];
    const float* W2    = (const float*)d_in[7];
    const float* b2    = (const float*)d_in[8];
    const float* plam  = (const float*)d_in[9];
    float* out = (float*)d_out;

    // 1) H = z @ W1 for both views
    k_gemm1<<<dim3(NH / 128, NB / 128, 2), 256>>>(z1, z2, W1);
    // 2) BN stats (partial col sums) + finalize scale/shift
    k_bnstats<<<dim3(NH / 256, 32, 2), 256>>>();
    k_bnfin<<<(2 * NH) / 256, 256>>>(gamma, beta);
    // 3) Q = relu(bn(H)) @ W2 + b2
    k_gemm2<<<dim3(NE / 128, NB / 128, 2), 256>>>(W2, b2);
    // 4) row inverse norms for p1, p2, q1, q2
    k_norms<<<dim3(NB / 8, 4), 256>>>(p1, p2);
    // 5) M = v2n^T v1n / lamda_inv (split-K partials + reduce)
    k_gemmM<<<dim3(NE / 64, NE / 64, 16), 256>>>(p1, p2);
    k_Mred<<<dim3((NE * NE) / 256, 2), 256>>>(plam);
    // 6) M2 = M @ M, then traces and final combine
    k_M2<<<dim3(NE / 64, NE / 64, 2), 256>>>();
    k_traces<<<dim3(32, 2), 256>>>();
    k_final<<<1, 1>>>(plam, out);
}

// round 12
// speedup vs baseline: 3.6168x; 3.6168x over previous
#include <cuda_runtime.h>
#include <math.h>
#include <stdint.h>

// Problem dims (fixed by the reference)
#define NB 8192   // batch
#define NE 256    // embedding
#define NH 4096   // hidden
#define BN_EPS 1e-5f

// ---------------------------------------------------------------------------
// Scratch (device globals: allocation-free)
// ---------------------------------------------------------------------------
__device__ float g_H[2][NB * NH];          // 256 MB: pre-BN hidden per view
__device__ float g_Q[2][NB * NE];          // 16 MB: predictor outputs
__device__ float g_psum[2][64][NH];        // per-128-rowblock partial col sums
__device__ float g_psumsq[2][64][NH];
__device__ float g_scale[2][NH];
__device__ float g_shift[2][NH];
__device__ float g_inorm[4][NB];           // inv row norms: p1,p2,q1,q2
__device__ float g_VT[2][NE * NB];         // VT[0]=q2n^T, VT[1]=q1n^T  [E][B]
__device__ float g_Mp[2][16][NE * NE];     // split-K partials of M
__device__ float g_M[2][NE * NE];
__device__ float g_M2[2][NE * NE];
__device__ float g_tp[2][32][4];

// ---------------------------------------------------------------------------
// Baseline-PTX helpers (compute_103-safe: cp.async / ldmatrix / mma.sync)
// ---------------------------------------------------------------------------
__device__ __forceinline__ uint32_t smem_u32(const void* p) {
    uint32_t a;
    asm("{ .reg .u64 t; cvta.to.shared.u64 t, %1; cvt.u32.u64 %0, t; }"
        : "=r"(a) : "l"(p));
    return a;
}

__device__ __forceinline__ void cp16(uint32_t dst, const void* src) {
    asm volatile("cp.async.cg.shared.global [%0], [%1], 16;" :: "r"(dst), "l"(src));
}
#define CP_COMMIT() asm volatile("cp.async.commit_group;" ::: "memory")
#define CP_WAIT0()  asm volatile("cp.async.wait_group 0;" ::: "memory")

__device__ __forceinline__ void ldsm4(uint32_t* r, uint32_t a) {
    asm volatile("ldmatrix.sync.aligned.m8n8.x4.shared.b16 {%0,%1,%2,%3}, [%4];"
                 : "=r"(r[0]), "=r"(r[1]), "=r"(r[2]), "=r"(r[3]) : "r"(a));
}

__device__ __forceinline__ void mma8(float* d, const uint32_t* a, const uint32_t* b) {
    asm volatile(
        "mma.sync.aligned.m16n8k8.row.col.f32.tf32.tf32.f32 "
        "{%0,%1,%2,%3}, {%4,%5,%6,%7}, {%8,%9}, {%0,%1,%2,%3};"
        : "+f"(d[0]), "+f"(d[1]), "+f"(d[2]), "+f"(d[3])
        : "r"(a[0]), "r"(a[1]), "r"(a[2]), "r"(a[3]), "r"(b[0]), "r"(b[1]));
}

// SMEM byte offsets (relative to 128B-aligned base)
// A tile: 128 rows x 128B (swizzled), double buffered
// B tile: 32 k-rows x 544B pitch (128 n-floats + 32B pad -> conflict-free LDS)
#define SA0 0
#define SA1 16384
#define SB0 32768
#define SB1 50176
#define SMEM_TOT 67584
#define SMEM_DYN (SMEM_TOT + 128)
#define BPITCH 544

#define ASWZ(row, colb) ((row) * 128 + ((colb) ^ (((row) & 7) << 4)))

// ---------------------------------------------------------------------------
// GEMM1: H[v] = z_v @ W1  (8192x256 @ 256x4096), tf32 mma.sync
// + fused BN partial column sums (per 128-row block) in epilogue.
// grid (NH/128=32, NB/128=64, 2), 256 threads
// ---------------------------------------------------------------------------
__global__ __launch_bounds__(256) void k_gemm1(const float* __restrict__ z1,
                                               const float* __restrict__ z2,
                                               const float* __restrict__ W1) {
    extern __shared__ char smraw[];
    uint32_t sb0 = smem_u32(smraw);
    uint32_t pad = (128u - (sb0 & 127u)) & 127u;
    char* sm = smraw + pad;
    uint32_t sb = sb0 + pad;

    const int v = blockIdx.z;
    const float* __restrict__ A = v ? z2 : z1;
    const int m0 = blockIdx.y * 128, n0 = blockIdx.x * 128;
    const int tid = threadIdx.x;
    const int lane = tid & 31, wid = tid >> 5;
    const int gid = lane >> 2, tig = lane & 3;
    const int wm = (wid >> 2) * 64, wn = (wid & 3) * 32;

    // ldmatrix lane geometry
    const int q = lane >> 3, r7 = lane & 7;
    const int a_ld_row = wm + (q & 1) * 8 + r7;
    const uint32_t a_xor = (uint32_t)(r7 << 4);
    const int a_cb = (q >> 1) * 16;

    float d[4][4][4] = {};

    auto loadA = [&](int c, int buf) {
        uint32_t base = sb + (buf ? SA1 : SA0);
        const float* Ab = A + (size_t)m0 * NE + c * 32;
#pragma unroll
        for (int i = 0; i < 4; i++) {
            int e = i * 256 + tid;
            int row = e >> 3, colb = (e & 7) * 16;
            cp16(base + ASWZ(row, colb), Ab + (size_t)row * NE + (colb >> 2));
        }
    };
    auto loadB = [&](int c, int buf) {
        uint32_t base = sb + (buf ? SB1 : SB0);
        const float* Bb = W1 + (size_t)(c * 32) * NH + n0;
#pragma unroll
        for (int i = 0; i < 4; i++) {
            int e = i * 256 + tid;
            int kr = e >> 5, colb = (e & 31) * 16;
            cp16(base + kr * BPITCH + colb, Bb + (size_t)kr * NH + (colb >> 2));
        }
    };

    loadA(0, 0); loadB(0, 0); CP_COMMIT(); CP_WAIT0();
    __syncthreads();

    const int NC = NE / 32;  // 8
    for (int c = 0; c < NC; c++) {
        int cur = c & 1;
        if (c + 1 < NC) { loadA(c + 1, cur ^ 1); loadB(c + 1, cur ^ 1); CP_COMMIT(); }
        uint32_t abase = sb + (cur ? SA1 : SA0);
        int bbo = (cur ? SB1 : SB0);
#pragma unroll
        for (int s = 0; s < 4; s++) {
            uint32_t afr[4][4];
#pragma unroll
            for (int mt = 0; mt < 4; mt++) {
                int row = a_ld_row + mt * 16;
                uint32_t colb = (uint32_t)(s * 32 + a_cb) ^ a_xor;
                ldsm4(afr[mt], abase + row * 128 + colb);
            }
            uint32_t bfr[4][2];
#pragma unroll
            for (int nt = 0; nt < 4; nt++) {
                int bo = bbo + (s * 8 + tig) * BPITCH + (wn + nt * 8 + gid) * 4;
                bfr[nt][0] = *(const uint32_t*)(sm + bo);
                bfr[nt][1] = *(const uint32_t*)(sm + bo + 4 * BPITCH);
            }
#pragma unroll
            for (int mt = 0; mt < 4; mt++)
#pragma unroll
                for (int nt = 0; nt < 4; nt++)
                    mma8(d[mt][nt], afr[mt], bfr[nt]);
        }
        if (c + 1 < NC) CP_WAIT0();
        __syncthreads();
    }

    // epilogue: store C
    float* C = g_H[v];
#pragma unroll
    for (int mt = 0; mt < 4; mt++) {
        int r0 = m0 + wm + mt * 16 + gid;
#pragma unroll
        for (int nt = 0; nt < 4; nt++) {
            int cc = n0 + wn + nt * 8 + 2 * tig;
            *(float2*)&C[(size_t)r0 * NH + cc] = make_float2(d[mt][nt][0], d[mt][nt][1]);
            *(float2*)&C[(size_t)(r0 + 8) * NH + cc] = make_float2(d[mt][nt][2], d[mt][nt][3]);
        }
    }

    // fused BN partial sums over this block's 128 rows
    float s[4][2], ss[4][2];
#pragma unroll
    for (int nt = 0; nt < 4; nt++)
#pragma unroll
        for (int j = 0; j < 2; j++) {
            float a = 0.f, b = 0.f;
#pragma unroll
            for (int mt = 0; mt < 4; mt++) {
                float x = d[mt][nt][j], y = d[mt][nt][2 + j];
                a += x + y;
                b = fmaf(x, x, fmaf(y, y, b));
            }
            s[nt][j] = a; ss[nt][j] = b;
        }
#pragma unroll
    for (int o = 4; o <= 16; o <<= 1) {
#pragma unroll
        for (int nt = 0; nt < 4; nt++)
#pragma unroll
            for (int j = 0; j < 2; j++) {
                s[nt][j] += __shfl_xor_sync(0xffffffffu, s[nt][j], o);
                ss[nt][j] += __shfl_xor_sync(0xffffffffu, ss[nt][j], o);
            }
    }
    float* red = (float*)sm;  // [2 stats][2 wrow][128 col] = 512 floats
    int wrow = wid >> 2;
    if (gid == 0) {
#pragma unroll
        for (int nt = 0; nt < 4; nt++)
#pragma unroll
            for (int j = 0; j < 2; j++) {
                int col = wn + nt * 8 + 2 * tig + j;
                red[wrow * 128 + col] = s[nt][j];
                red[256 + wrow * 128 + col] = ss[nt][j];
            }
    }
    __syncthreads();
    {
        int col = tid & 127, stat = tid >> 7;
        float val = red[stat * 256 + col] + red[stat * 256 + 128 + col];
        if (stat == 0) g_psum[v][blockIdx.y][n0 + col] = val;
        else           g_psumsq[v][blockIdx.y][n0 + col] = val;
    }
}

// Finalize BN: scale/shift per (view, hidden unit). grid 32 x 256
__global__ void k_bnfin(const float* __restrict__ gamma,
                        const float* __restrict__ beta) {
    int i = blockIdx.x * 256 + threadIdx.x;
    int v = i >> 12;
    int h = i & (NH - 1);
    float s = 0.f, s2 = 0.f;
#pragma unroll
    for (int b = 0; b < 64; b++) { s += g_psum[v][b][h]; s2 += g_psumsq[v][b][h]; }
    float mu = s * (1.f / NB);
    float var = s2 * (1.f / NB) - mu * mu;
    float scl = rsqrtf(var + BN_EPS) * gamma[h];
    g_scale[v][h] = scl;
    g_shift[v][h] = fmaf(-mu, scl, beta[h]);
}

// ---------------------------------------------------------------------------
// GEMM2: Q[v] = relu(bn(H[v])) @ W2 + b2  (8192x4096 @ 4096x256)
// A transformed on the LDG->STS path. grid (2, 64, 2), 256 threads
// ---------------------------------------------------------------------------
__global__ __launch_bounds__(256) void k_gemm2(const float* __restrict__ W2,
                                               const float* __restrict__ b2) {
    extern __shared__ char smraw[];
    uint32_t sb0 = smem_u32(smraw);
    uint32_t pad = (128u - (sb0 & 127u)) & 127u;
    char* sm = smraw + pad;
    uint32_t sb = sb0 + pad;

    const int v = blockIdx.z;
    const float* __restrict__ A = g_H[v];
    const float* __restrict__ sc = g_scale[v];
    const float* __restrict__ sh = g_shift[v];
    const int m0 = blockIdx.y * 128, n0 = blockIdx.x * 128;
    const int tid = threadIdx.x;
    const int lane = tid & 31, wid = tid >> 5;
    const int gid = lane >> 2, tig = lane & 3;
    const int wm = (wid >> 2) * 64, wn = (wid & 3) * 32;
    const int q = lane >> 3, r7 = lane & 7;
    const int a_ld_row = wm + (q & 1) * 8 + r7;
    const uint32_t a_xor = (uint32_t)(r7 << 4);
    const int a_cb = (q >> 1) * 16;

    float d[4][4][4] = {};
    float4 areg[4];

    auto ldgA = [&](int c) {
        const float* Ab = A + (size_t)m0 * NH + c * 32;
#pragma unroll
        for (int i = 0; i < 4; i++) {
            int e = i * 256 + tid;
            int row = e >> 3, kc = (e & 7) * 4;
            areg[i] = *(const float4*)(Ab + (size_t)row * NH + kc);
        }
    };
    auto stsA = [&](int c, int buf) {
        char* base = sm + (buf ? SA1 : SA0);
#pragma unroll
        for (int i = 0; i < 4; i++) {
            int e = i * 256 + tid;
            int row = e >> 3, kc = (e & 7) * 4;
            float4 s4 = *(const float4*)(sc + c * 32 + kc);
            float4 t4 = *(const float4*)(sh + c * 32 + kc);
            float4 a;
            a.x = fmaxf(fmaf(areg[i].x, s4.x, t4.x), 0.f);
            a.y = fmaxf(fmaf(areg[i].y, s4.y, t4.y), 0.f);
            a.z = fmaxf(fmaf(areg[i].z, s4.z, t4.z), 0.f);
            a.w = fmaxf(fmaf(areg[i].w, s4.w, t4.w), 0.f);
            *(float4*)(base + ASWZ(row, kc * 4)) = a;
        }
    };
    auto loadB = [&](int c, int buf) {
        uint32_t base = sb + (buf ? SB1 : SB0);
        const float* Bb = W2 + (size_t)(c * 32) * NE + n0;
#pragma unroll
        for (int i = 0; i < 4; i++) {
            int e = i * 256 + tid;
            int kr = e >> 5, colb = (e & 31) * 16;
            cp16(base + kr * BPITCH + colb, Bb + (size_t)kr * NE + (colb >> 2));
        }
    };

    ldgA(0); loadB(0, 0); CP_COMMIT();
    stsA(0, 0);
    CP_WAIT0();
    __syncthreads();

    const int NC = NH / 32;  // 128
    for (int c = 0; c < NC; c++) {
        int cur = c & 1;
        if (c + 1 < NC) { ldgA(c + 1); loadB(c + 1, cur ^ 1); CP_COMMIT(); }
        uint32_t abase = sb + (cur ? SA1 : SA0);
        int bbo = (cur ? SB1 : SB0);
#pragma unroll
        for (int s = 0; s < 4; s++) {
            uint32_t afr[4][4];
#pragma unroll
            for (int mt = 0; mt < 4; mt++) {
                int row = a_ld_row + mt * 16;
                uint32_t colb = (uint32_t)(s * 32 + a_cb) ^ a_xor;
                ldsm4(afr[mt], abase + row * 128 + colb);
            }
            uint32_t bfr[4][2];
#pragma unroll
            for (int nt = 0; nt < 4; nt++) {
                int bo = bbo + (s * 8 + tig) * BPITCH + (wn + nt * 8 + gid) * 4;
                bfr[nt][0] = *(const uint32_t*)(sm + bo);
                bfr[nt][1] = *(const uint32_t*)(sm + bo + 4 * BPITCH);
            }
#pragma unroll
            for (int mt = 0; mt < 4; mt++)
#pragma unroll
                for (int nt = 0; nt < 4; nt++)
                    mma8(d[mt][nt], afr[mt], bfr[nt]);
        }
        if (c + 1 < NC) { stsA(c + 1, cur ^ 1); CP_WAIT0(); }
        __syncthreads();
    }

    float* C = g_Q[v];
#pragma unroll
    for (int mt = 0; mt < 4; mt++) {
        int r0 = m0 + wm + mt * 16 + gid;
#pragma unroll
        for (int nt = 0; nt < 4; nt++) {
            int cc = n0 + wn + nt * 8 + 2 * tig;
            float2 bias = *(const float2*)(b2 + cc);
            *(float2*)&C[(size_t)r0 * NE + cc] =
                make_float2(d[mt][nt][0] + bias.x, d[mt][nt][1] + bias.y);
            *(float2*)&C[(size_t)(r0 + 8) * NE + cc] =
                make_float2(d[mt][nt][2] + bias.x, d[mt][nt][3] + bias.y);
        }
    }
}

// ---------------------------------------------------------------------------
// M-GEMM (split-K): Mp[mec][s][i][j] = sum_{b in slice} v2n^T[i][b] * v1n[b][j]
// A = g_VT[mec] [E][B] (cp.async), B = p(scaled by inorm) [B][E] (manual STS)
// grid (2 j, 2 i, 2*16), K per split = 512
// ---------------------------------------------------------------------------
__global__ __launch_bounds__(256) void k_gemmM(const float* __restrict__ p1,
                                               const float* __restrict__ p2) {
    extern __shared__ char smraw[];
    uint32_t sb0 = smem_u32(smraw);
    uint32_t pad = (128u - (sb0 & 127u)) & 127u;
    char* sm = smraw + pad;
    uint32_t sb = sb0 + pad;

    const int mec = blockIdx.z >> 4;
    const int split = blockIdx.z & 15;
    const float* __restrict__ A = g_VT[mec];
    const float* __restrict__ P = mec ? p2 : p1;
    const float* __restrict__ nrm = g_inorm[mec];
    const int i0 = blockIdx.y * 128, j0 = blockIdx.x * 128;
    const int kbase = split * 512;
    const int tid = threadIdx.x;
    const int lane = tid & 31, wid = tid >> 5;
    const int gid = lane >> 2, tig = lane & 3;
    const int wm = (wid >> 2) * 64, wn = (wid & 3) * 32;
    const int q = lane >> 3, r7 = lane & 7;
    const int a_ld_row = wm + (q & 1) * 8 + r7;
    const uint32_t a_xor = (uint32_t)(r7 << 4);
    const int a_cb = (q >> 1) * 16;

    float d[4][4][4] = {};
    float4 breg[4];
    float bnrm[4];

    auto loadA = [&](int c, int buf) {
        uint32_t base = sb + (buf ? SA1 : SA0);
        const float* Ab = A + (size_t)i0 * NB + kbase + c * 32;
#pragma unroll
        for (int i = 0; i < 4; i++) {
            int e = i * 256 + tid;
            int row = e >> 3, colb = (e & 7) * 16;
            cp16(base + ASWZ(row, colb), Ab + (size_t)row * NB + (colb >> 2));
        }
    };
    auto ldgB = [&](int c) {
#pragma unroll
        for (int i = 0; i < 4; i++) {
            int e = i * 256 + tid;
            int kr = e >> 5, col = (e & 31) * 4;
            int b = kbase + c * 32 + kr;
            breg[i] = *(const float4*)(P + (size_t)b * NE + j0 + col);
            bnrm[i] = nrm[b];
        }
    };
    auto stsB = [&](int buf) {
        char* base = sm + (buf ? SB1 : SB0);
#pragma unroll
        for (int i = 0; i < 4; i++) {
            int e = i * 256 + tid;
            int kr = e >> 5, colb = (e & 31) * 16;
            float n = bnrm[i];
            *(float4*)(base + kr * BPITCH + colb) =
                make_float4(breg[i].x * n, breg[i].y * n, breg[i].z * n, breg[i].w * n);
        }
    };

    ldgB(0); loadA(0, 0); CP_COMMIT();
    stsB(0);
    CP_WAIT0();
    __syncthreads();

    const int NC = 16;  // 512 / 32
    for (int c = 0; c < NC; c++) {
        int cur = c & 1;
        if (c + 1 < NC) { ldgB(c + 1); loadA(c + 1, cur ^ 1); CP_COMMIT(); }
        uint32_t abase = sb + (cur ? SA1 : SA0);
        int bbo = (cur ? SB1 : SB0);
#pragma unroll
        for (int s = 0; s < 4; s++) {
            uint32_t afr[4][4];
#pragma unroll
            for (int mt = 0; mt < 4; mt++) {
                int row = a_ld_row + mt * 16;
                uint32_t colb = (uint32_t)(s * 32 + a_cb) ^ a_xor;
                ldsm4(afr[mt], abase + row * 128 + colb);
            }
            uint32_t bfr[4][2];
#pragma unroll
            for (int nt = 0; nt < 4; nt++) {
                int bo = bbo + (s * 8 + tig) * BPITCH + (wn + nt * 8 + gid) * 4;
                bfr[nt][0] = *(const uint32_t*)(sm + bo);
                bfr[nt][1] = *(const uint32_t*)(sm + bo + 4 * BPITCH);
            }
#pragma unroll
            for (int mt = 0; mt < 4; mt++)
#pragma unroll
                for (int nt = 0; nt < 4; nt++)
                    mma8(d[mt][nt], afr[mt], bfr[nt]);
        }
        if (c + 1 < NC) { stsB(cur ^ 1); CP_WAIT0(); }
        __syncthreads();
    }

    float* O = g_Mp[mec][split];
#pragma unroll
    for (int mt = 0; mt < 4; mt++) {
        int r0 = i0 + wm + mt * 16 + gid;
#pragma unroll
        for (int nt = 0; nt < 4; nt++) {
            int cc = j0 + wn + nt * 8 + 2 * tig;
            *(float2*)&O[(size_t)r0 * NE + cc] = make_float2(d[mt][nt][0], d[mt][nt][1]);
            *(float2*)&O[(size_t)(r0 + 8) * NE + cc] = make_float2(d[mt][nt][2], d[mt][nt][3]);
        }
    }
}

// ---------------------------------------------------------------------------
// Row inverse L2 norms for p1, p2, q1, q2
// ---------------------------------------------------------------------------
__global__ __launch_bounds__(256) void k_norms(const float* __restrict__ p1,
                                               const float* __restrict__ p2) {
    int mat = blockIdx.y;
    const float* X = (mat == 0) ? p1 : (mat == 1) ? p2 : g_Q[mat - 2];
    int row = blockIdx.x * 8 + (threadIdx.x >> 5);
    int lane = threadIdx.x & 31;
    const float* xr = X + (size_t)row * NE;
    float s = 0.f;
#pragma unroll
    for (int j = 0; j < NE; j += 32) {
        float x = xr[j + lane];
        s = fmaf(x, x, s);
    }
#pragma unroll
    for (int o = 16; o; o >>= 1) s += __shfl_xor_sync(0xffffffffu, s, o);
    if (lane == 0) g_inorm[mat][row] = 1.f / fmaxf(sqrtf(s), 1e-12f);
}

// transpose+normalize q2 -> VT[0], q1 -> VT[1]
__global__ __launch_bounds__(256) void k_transnorm() {
    __shared__ float t[32][33];
    int z = blockIdx.z;                 // 0: q2, 1: q1
    const float* X = g_Q[1 - z];
    const float* nrm = g_inorm[3 - z];
    float* O = g_VT[z];
    int bx = blockIdx.x * 32;           // over B
    int by = blockIdx.y * 32;           // over E
    int tx = threadIdx.x & 31, ty = threadIdx.x >> 5;
#pragma unroll
    for (int i = 0; i < 4; i++) {
        int r = bx + ty + 8 * i;
        t[ty + 8 * i][tx] = X[(size_t)r * NE + by + tx] * nrm[r];
    }
    __syncthreads();
#pragma unroll
    for (int i = 0; i < 4; i++)
        O[(size_t)(by + ty + 8 * i) * NB + bx + tx] = t[tx][ty + 8 * i];
}

// Reduce split-K partials and apply 1/lamda_inv. grid (256, 2)
__global__ void k_Mred(const float* __restrict__ plam) {
    int m = blockIdx.y;
    int i = blockIdx.x * 256 + threadIdx.x;
    float inv = 1.f / *plam;
    float s = 0.f;
#pragma unroll
    for (int ks = 0; ks < 16; ks++) s += g_Mp[m][ks][i];
    g_M[m][i] = s * inv;
}

// ---------------------------------------------------------------------------
// M2 = M @ M (256^3), traces, final scalar
// ---------------------------------------------------------------------------
__global__ __launch_bounds__(256) void k_M2() {
    const int m = blockIdx.z;
    const float* M = g_M[m];
    float* O = g_M2[m];
    __shared__ float As[16][64];
    __shared__ float Bs[16][64];
    const int tid = threadIdx.x;
    const int tx = tid & 15, ty = tid >> 4;
    const int i0 = blockIdx.y * 64, j0 = blockIdx.x * 64;
    const int ai = tid >> 2, ak = (tid & 3) * 4;
    const int bk = tid >> 4, bj = (tid & 15) * 4;
    float acc[4][4] = {};
    for (int kb = 0; kb < NE; kb += 16) {
        float4 av = *(const float4*)(M + (i0 + ai) * NE + kb + ak);
        float4 bv = *(const float4*)(M + (kb + bk) * NE + j0 + bj);
        __syncthreads();
        As[ak + 0][ai] = av.x; As[ak + 1][ai] = av.y;
        As[ak + 2][ai] = av.z; As[ak + 3][ai] = av.w;
        *(float4*)&Bs[bk][bj] = bv;
        __syncthreads();
#pragma unroll
        for (int k = 0; k < 16; k++) {
            float a[4], bb[4];
            *(float4*)a = *(const float4*)&As[k][ty * 4];
            *(float4*)bb = *(const float4*)&Bs[k][tx * 4];
#pragma unroll
            for (int ii = 0; ii < 4; ii++)
#pragma unroll
                for (int jj = 0; jj < 4; jj++)
                    acc[ii][jj] = fmaf(a[ii], bb[jj], acc[ii][jj]);
        }
    }
#pragma unroll
    for (int ii = 0; ii < 4; ii++)
#pragma unroll
        for (int jj = 0; jj < 4; jj++)
            O[(i0 + ty * 4 + ii) * NE + j0 + tx * 4 + jj] = acc[ii][jj];
}

__global__ __launch_bounds__(256) void k_traces() {
    const int m = blockIdx.y;
    const float* M = g_M[m];
    const float* M2 = g_M2[m];
    const int tid = threadIdx.x;
    const int idx0 = blockIdx.x * 2048;
    float t1 = 0.f, t2 = 0.f, t3 = 0.f, t4 = 0.f;
    for (int idx = idx0 + tid; idx < idx0 + 2048; idx += 256) {
        int i = idx >> 8, j = idx & 255;
        float mij = M[idx], mji = M[j * NE + i];
        float m2ij = M2[idx], m2ji = M2[j * NE + i];
        if (i == j) t1 += mij;
        t2 = fmaf(mij, mji, t2);
        t3 = fmaf(m2ij, mji, t3);
        t4 = fmaf(m2ij, m2ji, t4);
    }
    __shared__ float red[4][256];
    red[0][tid] = t1; red[1][tid] = t2; red[2][tid] = t3; red[3][tid] = t4;
    __syncthreads();
    for (int s = 128; s > 0; s >>= 1) {
        if (tid < s) {
            red[0][tid] += red[0][tid + s];
            red[1][tid] += red[1][tid + s];
            red[2][tid] += red[2][tid + s];
            red[3][tid] += red[3][tid + s];
        }
        __syncthreads();
    }
    if (tid < 4) g_tp[m][blockIdx.x][tid] = red[tid][0];
}

__global__ void k_final(const float* __restrict__ plam, float* __restrict__ out) {
    float t[2][4];
    for (int m = 0; m < 2; m++)
        for (int c = 0; c < 4; c++) {
            float s = 0.f;
            for (int b = 0; b < 32; b++) s += g_tp[m][b][c];
            t[m][c] = s;
        }
    float s0 = t[0][0] - 0.5f * t[0][1] + (1.f / 3.f) * t[0][2] - 0.25f * t[0][3];
    float s1 = t[1][0] - 0.5f * t[1][1] + (1.f / 3.f) * t[1][2] - 0.25f * t[1][3];
    float loss = (s0 + s1) * 0.5f / (float)NB;
    out[0] = -loss * (*plam);
}

// ---------------------------------------------------------------------------
// Launch
// ---------------------------------------------------------------------------
extern "C" void kernel_launch(void* const* d_in, const int* in_sizes, int n_in,
                              void* d_out, int out_size) {
    const float* z1    = (const float*)d_in[0];
    const float* z2    = (const float*)d_in[1];
    const float* p1    = (const float*)d_in[2];
    const float* p2    = (const float*)d_in[3];
    const float* W1    = (const float*)d_in[4];
    const float* gamma = (const float*)d_in[5];
    const float* beta  = (const float*)d_in[6];
    const float* W2    = (const float*)d_in[7];
    const float* b2    = (const float*)d_in[8];
    const float* plam  = (const float*)d_in[9];
    float* out = (float*)d_out;

    cudaFuncSetAttribute(k_gemm1, cudaFuncAttributeMaxDynamicSharedMemorySize, SMEM_DYN);
    cudaFuncSetAttribute(k_gemm2, cudaFuncAttributeMaxDynamicSharedMemorySize, SMEM_DYN);
    cudaFuncSetAttribute(k_gemmM, cudaFuncAttributeMaxDynamicSharedMemorySize, SMEM_DYN);

    // 1) H = z @ W1 (tf32 mma.sync) with fused BN partial stats
    k_gemm1<<<dim3(NH / 128, NB / 128, 2), 256, SMEM_DYN>>>(z1, z2, W1);
    k_bnfin<<<(2 * NH) / 256, 256>>>(gamma, beta);
    // 2) Q = relu(bn(H)) @ W2 + b2
    k_gemm2<<<dim3(NE / 128, NB / 128, 2), 256, SMEM_DYN>>>(W2, b2);
    // 3) norms + transpose/normalize q's
    k_norms<<<dim3(NB / 8, 4), 256>>>(p1, p2);
    k_transnorm<<<dim3(NB / 32, NE / 32, 2), 256>>>();
    // 4) M via split-K tf32 GEMM + deterministic reduce (applies 1/lamda_inv)
    k_gemmM<<<dim3(NE / 128, NE / 128, 32), 256, SMEM_DYN>>>(p1, p2);
    k_Mred<<<dim3((NE * NE) / 256, 2), 256>>>(plam);
    // 5) M2, traces, final
    k_M2<<<dim3(NE / 64, NE / 64, 2), 256>>>();
    k_traces<<<dim3(32, 2), 256>>>();
    k_final<<<1, 1>>>(plam, out);
}